// round 6
// baseline (speedup 1.0000x reference)
#include <cuda_runtime.h>
#include <cuda_bf16.h>
#include <math.h>
#include <stdint.h>

// Problem constants
#define BB   2
#define SS   2048
#define HH   16
#define DD   64
#define HID  1024
#define MM   (BB*SS)        // 4096
#define BH   (BB*HH)        // 32

// Scratch (device globals; allocation-guard safe)
__device__ float g_q[BH * SS * DD];   // [bh][s][d]
__device__ float g_k[BH * SS * DD];
__device__ float g_v[BH * SS * DD];
__device__ float g_ctx[MM * HID];     // [b*S+s][h*64+d]

// omega[l] = 10000^(-l/10)
__device__ __constant__ float OMEGA[10] = {
    1.0f, 0.3981071705534972f, 0.15848931924611134f, 0.0630957344480193f,
    0.025118864315095794f, 0.01f, 0.003981071705534973f, 0.001584893192461114f,
    0.000630957344480193f, 0.00025118864315095795f
};

// ----------------------------------------------------------------------------
// TF32 helpers
// ----------------------------------------------------------------------------
__device__ __forceinline__ uint32_t f2tf32(float x) {
    uint32_t r;
    asm("cvt.rna.tf32.f32 %0, %1;" : "=r"(r) : "f"(x));
    return r;
}

__device__ __forceinline__ void mma_tf32(float* d, const uint32_t* a, const uint32_t* b) {
    asm volatile(
        "mma.sync.aligned.m16n8k8.row.col.f32.tf32.tf32.f32 "
        "{%0,%1,%2,%3}, {%4,%5,%6,%7}, {%8,%9}, {%0,%1,%2,%3};"
        : "+f"(d[0]), "+f"(d[1]), "+f"(d[2]), "+f"(d[3])
        : "r"(a[0]), "r"(a[1]), "r"(a[2]), "r"(a[3]), "r"(b[0]), "r"(b[1]));
}

// ----------------------------------------------------------------------------
// QKV projection (TF32 MMA, double-buffered): C = X @ W + b -> [bh][s][d],
// with RoPE fused into the epilogue for q and k.
// BM=128, BN=128, BK=16. Warp grid 4x2, warp tile 32x64.
// grid: (HID/128, MM/128, 3)
// ----------------------------------------------------------------------------
__global__ __launch_bounds__(256) void qkv_mma_kernel(
    const float* __restrict__ X,
    const float* __restrict__ Wq, const float* __restrict__ bq,
    const float* __restrict__ Wk, const float* __restrict__ bk,
    const float* __restrict__ Wv, const float* __restrict__ bv)
{
    const int z = blockIdx.z;
    const float* __restrict__ W    = (z == 0) ? Wq : (z == 1) ? Wk : Wv;
    const float* __restrict__ bias = (z == 0) ? bq : (z == 1) ? bk : bv;
    float* __restrict__ dst        = (z == 0) ? g_q : (z == 1) ? g_k : g_v;

    __shared__ uint32_t As[2][128][20];
    __shared__ uint32_t Bs[2][16][136];

    const int m0 = blockIdx.y * 128;
    const int n0 = blockIdx.x * 128;
    const int tid = threadIdx.x;
    const int wid = tid >> 5, lane = tid & 31;
    const int g = lane >> 2, t = lane & 3;
    const int wm = wid >> 1, wn = wid & 1;

    // staging-load geometry
    const int arow = tid >> 2,  ac4 = (tid & 3) * 4;    // + u*64 rows
    const int brow = tid >> 5,  bn4 = (tid & 31) * 4;   // + u*8 k-rows

    float acc[2][8][4];
#pragma unroll
    for (int i = 0; i < 2; i++)
#pragma unroll
        for (int j = 0; j < 8; j++)
#pragma unroll
            for (int r = 0; r < 4; r++) acc[i][j][r] = 0.0f;

    float4 ra[2], rb[2];
    // preload k0 = 0
#pragma unroll
    for (int u = 0; u < 2; u++) {
        ra[u] = *(const float4*)(X + (size_t)(m0 + arow + u * 64) * HID + ac4);
        rb[u] = *(const float4*)(W + (size_t)(brow + u * 8) * HID + n0 + bn4);
    }
#pragma unroll
    for (int u = 0; u < 2; u++) {
        uint32_t* pa = &As[0][arow + u * 64][ac4];
        pa[0] = f2tf32(ra[u].x); pa[1] = f2tf32(ra[u].y);
        pa[2] = f2tf32(ra[u].z); pa[3] = f2tf32(ra[u].w);
        uint32_t* pb = &Bs[0][brow + u * 8][bn4];
        pb[0] = f2tf32(rb[u].x); pb[1] = f2tf32(rb[u].y);
        pb[2] = f2tf32(rb[u].z); pb[3] = f2tf32(rb[u].w);
    }
    __syncthreads();

    int buf = 0;
    for (int k0 = 0; k0 < HID; k0 += 16) {
        const bool has_next = (k0 + 16 < HID);
        if (has_next) {
#pragma unroll
            for (int u = 0; u < 2; u++) {
                ra[u] = *(const float4*)(X + (size_t)(m0 + arow + u * 64) * HID + k0 + 16 + ac4);
                rb[u] = *(const float4*)(W + (size_t)(k0 + 16 + brow + u * 8) * HID + n0 + bn4);
            }
        }

#pragma unroll
        for (int ks = 0; ks < 2; ks++) {
            const int kb = ks * 8;
            uint32_t a[2][4], b[8][2];
#pragma unroll
            for (int ma = 0; ma < 2; ma++) {
                int row = wm * 32 + ma * 16 + g;
                a[ma][0] = As[buf][row][kb + t];
                a[ma][1] = As[buf][row + 8][kb + t];
                a[ma][2] = As[buf][row][kb + t + 4];
                a[ma][3] = As[buf][row + 8][kb + t + 4];
            }
#pragma unroll
            for (int na = 0; na < 8; na++) {
                int n = wn * 64 + na * 8 + g;
                b[na][0] = Bs[buf][kb + t][n];
                b[na][1] = Bs[buf][kb + t + 4][n];
            }
#pragma unroll
            for (int ma = 0; ma < 2; ma++)
#pragma unroll
                for (int na = 0; na < 8; na++)
                    mma_tf32(acc[ma][na], a[ma], b[na]);
        }

        if (has_next) {
            const int nb = buf ^ 1;
#pragma unroll
            for (int u = 0; u < 2; u++) {
                uint32_t* pa = &As[nb][arow + u * 64][ac4];
                pa[0] = f2tf32(ra[u].x); pa[1] = f2tf32(ra[u].y);
                pa[2] = f2tf32(ra[u].z); pa[3] = f2tf32(ra[u].w);
                uint32_t* pb = &Bs[nb][brow + u * 8][bn4];
                pb[0] = f2tf32(rb[u].x); pb[1] = f2tf32(rb[u].y);
                pb[2] = f2tf32(rb[u].z); pb[3] = f2tf32(rb[u].w);
            }
        }
        __syncthreads();
        buf ^= 1;
    }

    // Epilogue: +bias, fused axial RoPE (q,k only), scatter to [bh][s][d]
    const bool do_rope = (z < 2);
#pragma unroll
    for (int ma = 0; ma < 2; ma++) {
#pragma unroll
        for (int na = 0; na < 8; na++) {
            int m = m0 + wm * 32 + ma * 16 + g;
            int n = n0 + wn * 64 + na * 8 + 2 * t;
            float b0 = bias[n], b1 = bias[n + 1];
            int h = n >> 6, d = n & 63;

            float y00 = acc[ma][na][0] + b0;   // row m,   col d
            float y01 = acc[ma][na][1] + b1;   // row m,   col d+1
            float y10 = acc[ma][na][2] + b0;   // row m+8
            float y11 = acc[ma][na][3] + b1;

            if (do_rope && d < 60) {
                int seg = d / 20;
                int j = d - seg * 20;              // even, [0,18]
                int l0 = (j < 10) ? j : j - 10;
                int l1 = (j + 1 < 10) ? j + 1 : j - 9;
                float om0 = OMEGA[l0], om1 = OMEGA[l1];
                // row m
                {
                    int s = m & 2047;
                    int pos = (seg == 0) ? (s >> 8) : (seg == 1) ? ((s >> 4) & 15) : (s & 15);
                    float p = (float)pos;
                    float sn0, cs0, sn1, cs1;
                    sincosf(p * om0, &sn0, &cs0);
                    sincosf(p * om1, &sn1, &cs1);
                    float r0 = y00 * cs0 - y01 * sn0;
                    float r1 = y01 * cs1 + y00 * sn1;
                    y00 = r0; y01 = r1;
                }
                // row m+8
                {
                    int s = (m + 8) & 2047;
                    int pos = (seg == 0) ? (s >> 8) : (seg == 1) ? ((s >> 4) & 15) : (s & 15);
                    float p = (float)pos;
                    float sn0, cs0, sn1, cs1;
                    sincosf(p * om0, &sn0, &cs0);
                    sincosf(p * om1, &sn1, &cs1);
                    float r0 = y10 * cs0 - y11 * sn0;
                    float r1 = y11 * cs1 + y10 * sn1;
                    y10 = r0; y11 = r1;
                }
            }
            {
                int b = m >> 11, s = m & 2047;
                float2 v = { y00, y01 };
                *(float2*)(dst + (((size_t)((b << 4) + h)) * SS + s) * DD + d) = v;
            }
            {
                int m2 = m + 8;
                int b = m2 >> 11, s = m2 & 2047;
                float2 v = { y10, y11 };
                *(float2*)(dst + (((size_t)((b << 4) + h)) * SS + s) * DD + d) = v;
            }
        }
    }
}

// ----------------------------------------------------------------------------
// Fused flash attention: softmax(Q K^T * 0.125) @ V -> g_ctx (flat layout).
// Block = one (bh, 128-row Q tile); 8 warps x 16 rows. 64-key K-tiles,
// double-buffered K/V smem with register-staged prefetch.
// Scale 0.125 = 2^-3 folded into Q at load (exact under TF32 rounding).
// grid: (SS/128, BH), 256 threads, ~138 KB dynamic smem.
// ----------------------------------------------------------------------------
#define QS_STR 68
#define KS_STR 68
#define VS_STR 72
#define PS_STR 68
#define SM_Q 0
#define SM_K (SM_Q + 128 * QS_STR)
#define SM_V (SM_K + 2 * 64 * KS_STR)
#define SM_P (SM_V + 2 * 64 * VS_STR)
#define FLASH_SMEM_WORDS (SM_P + 128 * PS_STR)
#define FLASH_SMEM_BYTES (FLASH_SMEM_WORDS * 4)

__global__ __launch_bounds__(256) void flash_kernel()
{
    extern __shared__ uint32_t sm[];
    uint32_t* __restrict__ Qs = sm + SM_Q;
    uint32_t* __restrict__ Ps = sm + SM_P;

    const int bh = blockIdx.y;
    const int q0 = blockIdx.x * 128;
    const float* __restrict__ Q = g_q + (size_t)bh * SS * DD;
    const float* __restrict__ K = g_k + (size_t)bh * SS * DD;
    const float* __restrict__ V = g_v + (size_t)bh * SS * DD;

    const int tid = threadIdx.x;
    const int wid = tid >> 5, lane = tid & 31;
    const int g = lane >> 2, t = lane & 3;
    const int mr = wid * 16;

    const int krow = tid >> 4, kc4 = (tid & 15) * 4;   // + u*16 rows, u<4

    // Load Q tile (128 x 64), pre-scaled by 0.125 (exact power of 2)
#pragma unroll
    for (int i = tid; i < 128 * 16; i += 256) {
        int row = i >> 4, c4 = (i & 15) * 4;
        float4 v = *(const float4*)(Q + (size_t)(q0 + row) * DD + c4);
        Qs[row * QS_STR + c4 + 0] = f2tf32(0.125f * v.x);
        Qs[row * QS_STR + c4 + 1] = f2tf32(0.125f * v.y);
        Qs[row * QS_STR + c4 + 2] = f2tf32(0.125f * v.z);
        Qs[row * QS_STR + c4 + 3] = f2tf32(0.125f * v.w);
    }

    // Preload K/V tile 0 into buf 0
    float4 rk[4], rv[4];
#pragma unroll
    for (int u = 0; u < 4; u++) {
        rk[u] = *(const float4*)(K + (size_t)(krow + u * 16) * DD + kc4);
        rv[u] = *(const float4*)(V + (size_t)(krow + u * 16) * DD + kc4);
    }
#pragma unroll
    for (int u = 0; u < 4; u++) {
        uint32_t* pk = sm + SM_K + (krow + u * 16) * KS_STR + kc4;
        pk[0] = f2tf32(rk[u].x); pk[1] = f2tf32(rk[u].y);
        pk[2] = f2tf32(rk[u].z); pk[3] = f2tf32(rk[u].w);
        uint32_t* pv = sm + SM_V + (krow + u * 16) * VS_STR + kc4;
        pv[0] = f2tf32(rv[u].x); pv[1] = f2tf32(rv[u].y);
        pv[2] = f2tf32(rv[u].z); pv[3] = f2tf32(rv[u].w);
    }
    __syncthreads();

    float accO[8][4];
#pragma unroll
    for (int j = 0; j < 8; j++)
#pragma unroll
        for (int r = 0; r < 4; r++) accO[j][r] = 0.0f;
    float m0 = -1e30f, m1 = -1e30f, l0 = 0.0f, l1 = 0.0f;

    int buf = 0;
    for (int kt = 0; kt < SS; kt += 64) {
        const bool has_next = (kt + 64 < SS);
        if (has_next) {
#pragma unroll
            for (int u = 0; u < 4; u++) {
                rk[u] = *(const float4*)(K + (size_t)(kt + 64 + krow + u * 16) * DD + kc4);
                rv[u] = *(const float4*)(V + (size_t)(kt + 64 + krow + u * 16) * DD + kc4);
            }
        }
        const uint32_t* __restrict__ Ksb = sm + SM_K + buf * 64 * KS_STR;
        const uint32_t* __restrict__ Vsb = sm + SM_V + buf * 64 * VS_STR;

        // S = (0.125 Q) K^T  (warp tile 16 x 64)
        float accS[8][4];
#pragma unroll
        for (int j = 0; j < 8; j++)
#pragma unroll
            for (int r = 0; r < 4; r++) accS[j][r] = 0.0f;

#pragma unroll
        for (int kb = 0; kb < 8; kb++) {
            uint32_t a[4];
            a[0] = Qs[(mr + g) * QS_STR + kb * 8 + t];
            a[1] = Qs[(mr + g + 8) * QS_STR + kb * 8 + t];
            a[2] = Qs[(mr + g) * QS_STR + kb * 8 + t + 4];
            a[3] = Qs[(mr + g + 8) * QS_STR + kb * 8 + t + 4];
#pragma unroll
            for (int nf = 0; nf < 8; nf++) {
                uint32_t b[2];
                b[0] = Ksb[(nf * 8 + g) * KS_STR + kb * 8 + t];
                b[1] = Ksb[(nf * 8 + g) * KS_STR + kb * 8 + t + 4];
                mma_tf32(accS[nf], a, b);
            }
        }

        // Online softmax (rows mr+g and mr+g+8; quad = 4 lanes share a row)
        float r0 = -1e30f, r1 = -1e30f;
#pragma unroll
        for (int nf = 0; nf < 8; nf++) {
            r0 = fmaxf(r0, fmaxf(accS[nf][0], accS[nf][1]));
            r1 = fmaxf(r1, fmaxf(accS[nf][2], accS[nf][3]));
        }
        r0 = fmaxf(r0, __shfl_xor_sync(0xffffffffu, r0, 1));
        r0 = fmaxf(r0, __shfl_xor_sync(0xffffffffu, r0, 2));
        r1 = fmaxf(r1, __shfl_xor_sync(0xffffffffu, r1, 1));
        r1 = fmaxf(r1, __shfl_xor_sync(0xffffffffu, r1, 2));

        float mn0 = fmaxf(m0, r0);
        float mn1 = fmaxf(m1, r1);
        float al0 = __expf(m0 - mn0);
        float al1 = __expf(m1 - mn1);
        m0 = mn0; m1 = mn1;

        float s0 = 0.0f, s1 = 0.0f;
#pragma unroll
        for (int nf = 0; nf < 8; nf++) {
            float p00 = __expf(accS[nf][0] - m0);
            float p01 = __expf(accS[nf][1] - m0);
            float p10 = __expf(accS[nf][2] - m1);
            float p11 = __expf(accS[nf][3] - m1);
            s0 += p00 + p01;
            s1 += p10 + p11;
            int c = nf * 8 + 2 * t;
            Ps[(mr + g) * PS_STR + c]         = f2tf32(p00);
            Ps[(mr + g) * PS_STR + c + 1]     = f2tf32(p01);
            Ps[(mr + g + 8) * PS_STR + c]     = f2tf32(p10);
            Ps[(mr + g + 8) * PS_STR + c + 1] = f2tf32(p11);
        }
        s0 += __shfl_xor_sync(0xffffffffu, s0, 1);
        s0 += __shfl_xor_sync(0xffffffffu, s0, 2);
        s1 += __shfl_xor_sync(0xffffffffu, s1, 1);
        s1 += __shfl_xor_sync(0xffffffffu, s1, 2);
        l0 = l0 * al0 + s0;
        l1 = l1 * al1 + s1;

#pragma unroll
        for (int nf = 0; nf < 8; nf++) {
            accO[nf][0] *= al0;
            accO[nf][1] *= al0;
            accO[nf][2] *= al1;
            accO[nf][3] *= al1;
        }
        __syncwarp();   // P rows are warp-private

        // O += P @ V
#pragma unroll
        for (int kb = 0; kb < 8; kb++) {
            uint32_t a[4];
            a[0] = Ps[(mr + g) * PS_STR + kb * 8 + t];
            a[1] = Ps[(mr + g + 8) * PS_STR + kb * 8 + t];
            a[2] = Ps[(mr + g) * PS_STR + kb * 8 + t + 4];
            a[3] = Ps[(mr + g + 8) * PS_STR + kb * 8 + t + 4];
#pragma unroll
            for (int nf = 0; nf < 8; nf++) {
                uint32_t b[2];
                b[0] = Vsb[(kb * 8 + t) * VS_STR + nf * 8 + g];
                b[1] = Vsb[(kb * 8 + t + 4) * VS_STR + nf * 8 + g];
                mma_tf32(accO[nf], a, b);
            }
        }

        if (has_next) {
            const int nb = buf ^ 1;
#pragma unroll
            for (int u = 0; u < 4; u++) {
                uint32_t* pk = sm + SM_K + (nb * 64 + krow + u * 16) * KS_STR + kc4;
                pk[0] = f2tf32(rk[u].x); pk[1] = f2tf32(rk[u].y);
                pk[2] = f2tf32(rk[u].z); pk[3] = f2tf32(rk[u].w);
                uint32_t* pv = sm + SM_V + (nb * 64 + krow + u * 16) * VS_STR + kc4;
                pv[0] = f2tf32(rv[u].x); pv[1] = f2tf32(rv[u].y);
                pv[2] = f2tf32(rv[u].z); pv[3] = f2tf32(rv[u].w);
            }
        }
        __syncthreads();
        buf ^= 1;
    }

    // Epilogue: normalize, write flat ctx layout
    const float inv0 = 1.0f / l0;
    const float inv1 = 1.0f / l1;
    const int bb = bh >> 4, h = bh & 15;
    const int s0r = q0 + mr + g;
#pragma unroll
    for (int nf = 0; nf < 8; nf++) {
        int d = nf * 8 + 2 * t;
        float2 v0 = { accO[nf][0] * inv0, accO[nf][1] * inv0 };
        float2 v1 = { accO[nf][2] * inv1, accO[nf][3] * inv1 };
        *(float2*)(g_ctx + ((size_t)(bb * SS + s0r)) * HID + h * DD + d) = v0;
        *(float2*)(g_ctx + ((size_t)(bb * SS + s0r + 8)) * HID + h * DD + d) = v1;
    }
}

// ----------------------------------------------------------------------------
// Output projection (TF32 MMA, double-buffered): out = ctx @ Wo + bo.
// ----------------------------------------------------------------------------
__global__ __launch_bounds__(256) void oproj_mma_kernel(
    const float* __restrict__ Wo, const float* __restrict__ bo,
    float* __restrict__ out)
{
    __shared__ uint32_t As[2][128][20];
    __shared__ uint32_t Bs[2][16][136];

    const int m0 = blockIdx.y * 128;
    const int n0 = blockIdx.x * 128;
    const int tid = threadIdx.x;
    const int wid = tid >> 5, lane = tid & 31;
    const int g = lane >> 2, t = lane & 3;
    const int wm = wid >> 1, wn = wid & 1;

    const int arow = tid >> 2,  ac4 = (tid & 3) * 4;
    const int brow = tid >> 5,  bn4 = (tid & 31) * 4;

    float acc[2][8][4];
#pragma unroll
    for (int i = 0; i < 2; i++)
#pragma unroll
        for (int j = 0; j < 8; j++)
#pragma unroll
            for (int r = 0; r < 4; r++) acc[i][j][r] = 0.0f;

    float4 ra[2], rb[2];
#pragma unroll
    for (int u = 0; u < 2; u++) {
        ra[u] = *(const float4*)(g_ctx + (size_t)(m0 + arow + u * 64) * HID + ac4);
        rb[u] = *(const float4*)(Wo + (size_t)(brow + u * 8) * HID + n0 + bn4);
    }
#pragma unroll
    for (int u = 0; u < 2; u++) {
        uint32_t* pa = &As[0][arow + u * 64][ac4];
        pa[0] = f2tf32(ra[u].x); pa[1] = f2tf32(ra[u].y);
        pa[2] = f2tf32(ra[u].z); pa[3] = f2tf32(ra[u].w);
        uint32_t* pb = &Bs[0][brow + u * 8][bn4];
        pb[0] = f2tf32(rb[u].x); pb[1] = f2tf32(rb[u].y);
        pb[2] = f2tf32(rb[u].z); pb[3] = f2tf32(rb[u].w);
    }
    __syncthreads();

    int buf = 0;
    for (int k0 = 0; k0 < HID; k0 += 16) {
        const bool has_next = (k0 + 16 < HID);
        if (has_next) {
#pragma unroll
            for (int u = 0; u < 2; u++) {
                ra[u] = *(const float4*)(g_ctx + (size_t)(m0 + arow + u * 64) * HID + k0 + 16 + ac4);
                rb[u] = *(const float4*)(Wo + (size_t)(k0 + 16 + brow + u * 8) * HID + n0 + bn4);
            }
        }

#pragma unroll
        for (int ks = 0; ks < 2; ks++) {
            const int kb = ks * 8;
            uint32_t a[2][4], b[8][2];
#pragma unroll
            for (int ma = 0; ma < 2; ma++) {
                int row = wm * 32 + ma * 16 + g;
                a[ma][0] = As[buf][row][kb + t];
                a[ma][1] = As[buf][row + 8][kb + t];
                a[ma][2] = As[buf][row][kb + t + 4];
                a[ma][3] = As[buf][row + 8][kb + t + 4];
            }
#pragma unroll
            for (int na = 0; na < 8; na++) {
                int n = wn * 64 + na * 8 + g;
                b[na][0] = Bs[buf][kb + t][n];
                b[na][1] = Bs[buf][kb + t + 4][n];
            }
#pragma unroll
            for (int ma = 0; ma < 2; ma++)
#pragma unroll
                for (int na = 0; na < 8; na++)
                    mma_tf32(acc[ma][na], a[ma], b[na]);
        }

        if (has_next) {
            const int nb = buf ^ 1;
#pragma unroll
            for (int u = 0; u < 2; u++) {
                uint32_t* pa = &As[nb][arow + u * 64][ac4];
                pa[0] = f2tf32(ra[u].x); pa[1] = f2tf32(ra[u].y);
                pa[2] = f2tf32(ra[u].z); pa[3] = f2tf32(ra[u].w);
                uint32_t* pb = &Bs[nb][brow + u * 8][bn4];
                pb[0] = f2tf32(rb[u].x); pb[1] = f2tf32(rb[u].y);
                pb[2] = f2tf32(rb[u].z); pb[3] = f2tf32(rb[u].w);
            }
        }
        __syncthreads();
        buf ^= 1;
    }

#pragma unroll
    for (int ma = 0; ma < 2; ma++) {
#pragma unroll
        for (int na = 0; na < 8; na++) {
            int m = m0 + wm * 32 + ma * 16 + g;
            int n = n0 + wn * 64 + na * 8 + 2 * t;
            float b0 = bo[n], b1 = bo[n + 1];
            float2 v0 = { acc[ma][na][0] + b0, acc[ma][na][1] + b1 };
            float2 v1 = { acc[ma][na][2] + b0, acc[ma][na][3] + b1 };
            *(float2*)(out + (size_t)m * HID + n) = v0;
            *(float2*)(out + (size_t)(m + 8) * HID + n) = v1;
        }
    }
}

// ----------------------------------------------------------------------------
extern "C" void kernel_launch(void* const* d_in, const int* in_sizes, int n_in,
                              void* d_out, int out_size)
{
    const float* X  = (const float*)d_in[0];
    const float* Wq = (const float*)d_in[1];
    const float* bq = (const float*)d_in[2];
    const float* Wk = (const float*)d_in[3];
    const float* bk = (const float*)d_in[4];
    const float* Wv = (const float*)d_in[5];
    const float* bv = (const float*)d_in[6];
    const float* Wo = (const float*)d_in[7];
    const float* bo = (const float*)d_in[8];
    float* out = (float*)d_out;

    // Idempotent, not a stream op — safe under graph capture, no static guards.
    cudaFuncSetAttribute(flash_kernel,
                         cudaFuncAttributeMaxDynamicSharedMemorySize,
                         FLASH_SMEM_BYTES);

    qkv_mma_kernel<<<dim3(HID / 128, MM / 128, 3), 256>>>(X, Wq, bq, Wk, bk, Wv, bv);

    flash_kernel<<<dim3(SS / 128, BH), 256, FLASH_SMEM_BYTES>>>();

    oproj_mma_kernel<<<dim3(HID / 128, MM / 128), 256>>>(Wo, bo, out);
}